// round 4
// baseline (speedup 1.0000x reference)
#include <cuda_runtime.h>
#include <math.h>

// Shapes fixed by the problem instance.
#define B_SZ 2048
#define P_SZ 4
#define N_SZ 128
#define D_SZ 1024
#define S_SZ (N_SZ + 1)      // 129 samples: [last positive, negatives...]
#define EPS_F 1e-6f

#define THREADS 256
#define NWARP (THREADS / 32)

// Fixed-point accumulator: loss >= 0, quantized at 2^-32.
#define SCALE_D 4294967296.0

// Scratch (no cudaMalloc allowed). Reset by last block each run (replay-safe).
__device__ unsigned long long g_sum = 0ULL;
__device__ int g_count = 0;

__global__ __launch_bounds__(THREADS)
void contrastive_sim_kernel(const float* __restrict__ anchor,
                            const float* __restrict__ positives,
                            const float* __restrict__ negatives,
                            float* __restrict__ out) {
    const int b    = blockIdx.x;
    const int tid  = threadIdx.x;
    const int warp = tid >> 5;
    const int lane = tid & 31;

    __shared__ float4 sa[D_SZ / 4];   // anchor row, 4 KB
    __shared__ float  sims[S_SZ];
    __shared__ float  red[NWARP];
    __shared__ float  s_na;

    // ---- load anchor into smem, accumulate ||a||^2 ----
    const float4* ap = reinterpret_cast<const float4*>(anchor + (size_t)b * D_SZ);
    float asq = 0.f;
    #pragma unroll
    for (int i = tid; i < D_SZ / 4; i += THREADS) {
        float4 v = ap[i];
        sa[i] = v;
        asq += v.x * v.x + v.y * v.y + v.z * v.z + v.w * v.w;
    }
    #pragma unroll
    for (int o = 16; o; o >>= 1) asq += __shfl_down_sync(0xffffffffu, asq, o);
    if (lane == 0) red[warp] = asq;
    __syncthreads();
    if (warp == 0) {
        float v = (lane < NWARP) ? red[lane] : 0.f;
        #pragma unroll
        for (int o = 16; o; o >>= 1) v += __shfl_down_sync(0xffffffffu, v, o);
        if (lane == 0) s_na = fmaxf(sqrtf(v), EPS_F);
    }
    __syncthreads();
    const float na = s_na;

    // ---- each warp: cosine sim for its samples ----
    for (int s = warp; s < S_SZ; s += NWARP) {
        const float4* xp;
        if (s == 0)
            xp = reinterpret_cast<const float4*>(
                positives + ((size_t)b * P_SZ + (P_SZ - 1)) * D_SZ);
        else
            xp = reinterpret_cast<const float4*>(
                negatives + ((size_t)b * N_SZ + (s - 1)) * D_SZ);

        float dot = 0.f, nsq = 0.f;
        #pragma unroll
        for (int i = 0; i < D_SZ / 4 / 32; i++) {   // 8 coalesced float4 loads/lane
            int idx = i * 32 + lane;
            float4 x = xp[idx];
            float4 a = sa[idx];
            dot += a.x * x.x + a.y * x.y + a.z * x.z + a.w * x.w;
            nsq += x.x * x.x + x.y * x.y + x.z * x.z + x.w * x.w;
        }
        #pragma unroll
        for (int o = 16; o; o >>= 1) {
            dot += __shfl_down_sync(0xffffffffu, dot, o);
            nsq += __shfl_down_sync(0xffffffffu, nsq, o);
        }
        if (lane == 0) {
            float ns = fmaxf(sqrtf(nsq), EPS_F);
            sims[s] = dot / (na * ns);
        }
    }
    __syncthreads();

    // ---- warp 0: log-softmax over 129 values, then fixed-point atomic sum ----
    if (warp == 0) {
        float m = -1e30f;
        for (int s = lane; s < S_SZ; s += 32) m = fmaxf(m, sims[s]);
        #pragma unroll
        for (int o = 16; o; o >>= 1) m = fmaxf(m, __shfl_xor_sync(0xffffffffu, m, o));
        float sum = 0.f;
        for (int s = lane; s < S_SZ; s += 32) sum += __expf(sims[s] - m);
        #pragma unroll
        for (int o = 16; o; o >>= 1) sum += __shfl_xor_sync(0xffffffffu, sum, o);

        if (lane == 0) {
            float loss = -(sims[0] - m - __logf(sum));   // >= 0
            unsigned long long q =
                (unsigned long long)((double)loss * SCALE_D + 0.5);
            atomicAdd(&g_sum, q);          // exact, order-independent
            __threadfence();
            int prev = atomicAdd(&g_count, 1);
            if (prev == B_SZ - 1) {
                // Last block: all g_sum contributions are visible.
                unsigned long long total = atomicAdd(&g_sum, 0ULL);
                *out = (float)((double)total / SCALE_D / (double)B_SZ);
                g_sum = 0ULL;              // reset for next graph replay
                g_count = 0;
            }
        }
    }
}

extern "C" void kernel_launch(void* const* d_in, const int* in_sizes, int n_in,
                              void* d_out, int out_size) {
    const float* anchor    = (const float*)d_in[0];
    const float* positives = (const float*)d_in[1];
    const float* negatives = (const float*)d_in[2];
    float* out = (float*)d_out;

    contrastive_sim_kernel<<<B_SZ, THREADS>>>(anchor, positives, negatives, out);
}

// round 5
// speedup vs baseline: 1.0009x; 1.0009x over previous
#include <cuda_runtime.h>
#include <math.h>

// Shapes fixed by the problem instance.
#define B_SZ 2048
#define P_SZ 4
#define N_SZ 128
#define D_SZ 1024
#define S_SZ (N_SZ + 1)      // 129 samples: [last positive, negatives...]
#define EPS_F 1e-6f

#define THREADS 256
#define NWARP (THREADS / 32)

// Fixed-point accumulation of the (non-negative) per-batch losses at 2^-22
// resolution. Integer atomics are exact and commutative -> bit-deterministic.
#define SCALE_F   4194304.0f          // 2^22
#define INV_SCALE (1.0f / 8589934592.0f)  // 1 / (2^22 * 2048)

// Scratch (no cudaMalloc allowed). Reset by the last block each run.
__device__ unsigned long long g_sum = 0ULL;
__device__ int g_count = 0;

__global__ __launch_bounds__(THREADS)
void contrastive_fused_kernel(const float* __restrict__ anchor,
                              const float* __restrict__ positives,
                              const float* __restrict__ negatives,
                              float* __restrict__ out) {
    const int b    = blockIdx.x;
    const int tid  = threadIdx.x;
    const int warp = tid >> 5;
    const int lane = tid & 31;

    __shared__ float4 sa[D_SZ / 4];   // anchor row, 4 KB
    __shared__ float  sims[S_SZ];
    __shared__ float  red[NWARP];
    __shared__ float  s_na;

    // ---- load anchor into smem, accumulate ||a||^2 ----
    const float4* ap = reinterpret_cast<const float4*>(anchor + (size_t)b * D_SZ);
    float asq = 0.f;
    #pragma unroll
    for (int i = tid; i < D_SZ / 4; i += THREADS) {
        float4 v = ap[i];
        sa[i] = v;
        asq += v.x * v.x + v.y * v.y + v.z * v.z + v.w * v.w;
    }
    #pragma unroll
    for (int o = 16; o; o >>= 1) asq += __shfl_down_sync(0xffffffffu, asq, o);
    if (lane == 0) red[warp] = asq;
    __syncthreads();
    if (warp == 0) {
        float v = (lane < NWARP) ? red[lane] : 0.f;
        #pragma unroll
        for (int o = 16; o; o >>= 1) v += __shfl_down_sync(0xffffffffu, v, o);
        if (lane == 0) s_na = fmaxf(sqrtf(v), EPS_F);
    }
    __syncthreads();
    const float na = s_na;

    // ---- each warp: cosine sim for its samples ----
    for (int s = warp; s < S_SZ; s += NWARP) {
        const float4* xp;
        if (s == 0)
            xp = reinterpret_cast<const float4*>(
                positives + ((size_t)b * P_SZ + (P_SZ - 1)) * D_SZ);
        else
            xp = reinterpret_cast<const float4*>(
                negatives + ((size_t)b * N_SZ + (s - 1)) * D_SZ);

        float dot = 0.f, nsq = 0.f;
        #pragma unroll
        for (int i = 0; i < D_SZ / 4 / 32; i++) {   // 8 coalesced float4 loads/lane
            int idx = i * 32 + lane;
            float4 x = xp[idx];
            float4 a = sa[idx];
            dot += a.x * x.x + a.y * x.y + a.z * x.z + a.w * x.w;
            nsq += x.x * x.x + x.y * x.y + x.z * x.z + x.w * x.w;
        }
        #pragma unroll
        for (int o = 16; o; o >>= 1) {
            dot += __shfl_down_sync(0xffffffffu, dot, o);
            nsq += __shfl_down_sync(0xffffffffu, nsq, o);
        }
        if (lane == 0) {
            float ns = fmaxf(sqrtf(nsq), EPS_F);
            sims[s] = dot / (na * ns);
        }
    }
    __syncthreads();

    // ---- warp 0: log-softmax over 129 values, fixed-point atomic sum ----
    if (warp == 0) {
        float m = -1e30f;
        for (int s = lane; s < S_SZ; s += 32) m = fmaxf(m, sims[s]);
        #pragma unroll
        for (int o = 16; o; o >>= 1) m = fmaxf(m, __shfl_xor_sync(0xffffffffu, m, o));
        float sum = 0.f;
        for (int s = lane; s < S_SZ; s += 32) sum += __expf(sims[s] - m);
        #pragma unroll
        for (int o = 16; o; o >>= 1) sum += __shfl_xor_sync(0xffffffffu, sum, o);

        if (lane == 0) {
            float loss = -(sims[0] - m - __logf(sum));   // >= 0
            unsigned long long q =
                (unsigned long long)(loss * SCALE_F + 0.5f);
            atomicAdd(&g_sum, q);   // relaxed device atomic (exact integer sum)

            // Release-ordered counter bump: orders this block's g_sum add
            // before the count becomes visible. NO gpu-scope fence here --
            // __threadfence() would emit CCTL.IVALL (full L1D flush) in
            // every block and wreck the streaming pipeline.
            int prev;
            asm volatile(
                "atom.release.gpu.global.add.s32 %0, [%1], 1;"
                : "=r"(prev) : "l"(&g_count) : "memory");

            if (prev == B_SZ - 1) {
                // Last block: acquire-load pairs with the release-adds above,
                // so every block's g_sum contribution is visible.
                unsigned long long total;
                asm volatile(
                    "ld.acquire.gpu.global.b64 %0, [%1];"
                    : "=l"(total) : "l"(&g_sum) : "memory");
                *out = (float)total * INV_SCALE;
                g_sum = 0ULL;        // reset for next graph replay
                g_count = 0;
            }
        }
    }
}

extern "C" void kernel_launch(void* const* d_in, const int* in_sizes, int n_in,
                              void* d_out, int out_size) {
    const float* anchor    = (const float*)d_in[0];
    const float* positives = (const float*)d_in[1];
    const float* negatives = (const float*)d_in[2];
    float* out = (float*)d_out;

    contrastive_fused_kernel<<<B_SZ, THREADS>>>(anchor, positives, negatives, out);
}